// round 8
// baseline (speedup 1.0000x reference)
#include <cuda_runtime.h>

#define B_TOT 2048
#define H     51
#define KPW   56           // weight row k-extent (floats), 14 u2; cols 51..55 zero
#define PAIR  120          // floats per weight row-pair (30 u2 == 6 mod 8)
#define NJG   26           // row pairs (52 rows; row 51 zero)
#define WSZ   (NJG*PAIR)   // 3120 floats per gate matrix
#define HS    60           // h row stride (15 u2, odd -> bank-spread)
#define E     16
#define TPB   512          // kh(2) * eg(4) * ei2(2) * jg(32, 26 real)
#define XCH   40

typedef unsigned long long ull;

struct __align__(16) Smem {
    float l1r[WSZ], l1z[WSZ], l1n[WSZ];   // w_hh1
    float ir2[WSZ], iz2[WSZ], in2[WSZ];   // w_ih2
    float hr2[WSZ], hz2[WSZ], hn2[WSZ];   // w_hh2
    float wih1r[52], wih1z[52], wih1n[52];
    float bR1[52], bZ1[52], bIN1[52], bHN1[52];
    float bR2[52], bZ2[52], bIN2[52], bHN2[52];
    float wlin[KPW];
    float h1[2][E][HS];                   // ping-pong; floats 51..59 stay 0
    float h2[2][E][HS];
    float xbuf[E][XCH];
    float outp[E];
    float blin;
};

__device__ __forceinline__ void fma2(ull& d, ull a, ull b) {
    asm("fma.rn.f32x2 %0, %1, %2, %0;" : "+l"(d) : "l"(a), "l"(b));
}
__device__ __forceinline__ ull pack2(float a, float b) {
    ull r; asm("mov.b64 %0, {%1,%2};" : "=l"(r) : "f"(a), "f"(b)); return r;
}
__device__ __forceinline__ float sum2(ull v) {
    float a, b; asm("mov.b64 {%0,%1}, %2;" : "=f"(a), "=f"(b) : "l"(v));
    return a + b;
}
__device__ __forceinline__ float sigmoid_(float v) {
    return __fdividef(1.0f, 1.0f + __expf(-v));
}
__device__ __forceinline__ float tanh_(float v) {
    return __fdividef(2.0f, 1.0f + __expf(-2.0f * v)) - 1.0f;
}
__device__ __forceinline__ float gru_cell(float gr, float gz, float gin,
                                          float ghn, float ho) {
    float r = sigmoid_(gr);
    float z = sigmoid_(gz);
    float n = tanh_(fmaf(r, ghn, gin));
    return fmaf(z, ho - n, n);
}
// keep jj==kh cells, receive partner's (jj!=kh handled there) via 1 float shfl
#define XRED(g0, g1, A)                                                   \
    {                                                                     \
        float _a0 = sum2(A[0][0]), _a1 = sum2(A[0][1]);                   \
        float _b0 = sum2(A[1][0]), _b1 = sum2(A[1][1]);                   \
        float _k0 = kh ? _b0 : _a0, _k1 = kh ? _b1 : _a1;                 \
        float _s0 = kh ? _a0 : _b0, _s1 = kh ? _a1 : _b1;                 \
        g0 = _k0 + __shfl_xor_sync(0xFFFFFFFFu, _s0, 1);                  \
        g1 = _k1 + __shfl_xor_sync(0xFFFFFFFFu, _s1, 1);                  \
    }

// fill one padded gate matrix (gate g of a [153][51] row-major source)
__device__ __forceinline__ void fill_mat(float* dst, const float* src, int g, int tid) {
    for (int idx = tid; idx < WSZ; idx += TPB) {
        int jg = idx / PAIR, rem = idx - jg * PAIR;
        int jj = rem / KPW;                 // 0,1, or 2 => inter-pair pad
        int k  = rem - jj * KPW;
        float v = 0.f;
        if (jj < 2) {
            int j = jg * 2 + jj;
            if (j < H && k < H) v = src[(g * H + j) * H + k];
        }
        dst[idx] = v;
    }
}

__global__ void __launch_bounds__(TPB, 1) gru_stack_kernel(
    const float* __restrict__ x,
    const float* __restrict__ w_ih1, const float* __restrict__ w_hh1,
    const float* __restrict__ b_ih1, const float* __restrict__ b_hh1,
    const float* __restrict__ w_ih2, const float* __restrict__ w_hh2,
    const float* __restrict__ b_ih2, const float* __restrict__ b_hh2,
    const float* __restrict__ w_lin, const float* __restrict__ b_lin,
    float* __restrict__ out, int T, int F)
{
    extern __shared__ float smem_f[];
    Smem* s = reinterpret_cast<Smem*>(smem_f);

    const int tid = threadIdx.x;
    const int kh  = tid & 1;                 // k-half / owned jj
    const int m   = (tid >> 1) & 7;          // element pair id
    int jgr = tid >> 4; if (jgr > NJG - 1) jgr = NJG - 1;  // clone tail warps
    const int jg  = jgr;
    const int j0  = 2 * jg;
    const int jme = j0 + kh;                 // finalized gate row
    const int e0  = m, e1 = m + 8;           // finalized elements
    const int kb  = kh * 7;                  // u2 offset of k-half
    const int base = blockIdx.x * E;
    const int TF   = T + F;

    // ---------------- one-time init ----------------
    fill_mat(s->l1r, w_hh1, 0, tid); fill_mat(s->l1z, w_hh1, 1, tid); fill_mat(s->l1n, w_hh1, 2, tid);
    fill_mat(s->ir2, w_ih2, 0, tid); fill_mat(s->iz2, w_ih2, 1, tid); fill_mat(s->in2, w_ih2, 2, tid);
    fill_mat(s->hr2, w_hh2, 0, tid); fill_mat(s->hz2, w_hh2, 1, tid); fill_mat(s->hn2, w_hh2, 2, tid);
    for (int i = tid; i < 52; i += TPB) {
        bool v = (i < H);
        s->wih1r[i] = v ? w_ih1[i] : 0.f;
        s->wih1z[i] = v ? w_ih1[H + i] : 0.f;
        s->wih1n[i] = v ? w_ih1[2 * H + i] : 0.f;
        s->bR1[i]  = v ? (b_ih1[i] + b_hh1[i]) : 0.f;
        s->bZ1[i]  = v ? (b_ih1[H + i] + b_hh1[H + i]) : 0.f;
        s->bIN1[i] = v ? b_ih1[2 * H + i] : 0.f;
        s->bHN1[i] = v ? b_hh1[2 * H + i] : 0.f;
        s->bR2[i]  = v ? (b_ih2[i] + b_hh2[i]) : 0.f;
        s->bZ2[i]  = v ? (b_ih2[H + i] + b_hh2[H + i]) : 0.f;
        s->bIN2[i] = v ? b_ih2[2 * H + i] : 0.f;
        s->bHN2[i] = v ? b_hh2[2 * H + i] : 0.f;
    }
    for (int i = tid; i < KPW; i += TPB) s->wlin[i] = (i < H) ? w_lin[i] : 0.f;
    if (tid == 0) s->blin = b_lin[0];
    {
        float* h1f = &s->h1[0][0][0];
        float* h2f = &s->h2[0][0][0];
        for (int i = tid; i < 2 * E * HS; i += TPB) { h1f[i] = 0.f; h2f[i] = 0.f; }
        for (int i = tid; i < E; i += TPB) s->outp[i] = 0.f;
    }
    __syncthreads();

    int cur = 0;
    for (int t = 0; t < TF; ++t) {
        if (t < T && (t % XCH) == 0) {
            for (int i = tid; i < E * XCH; i += TPB) {
                int e = i / XCH, c = i - e * XCH;
                int tg = t + c;
                s->xbuf[e][c] = (tg < T) ? x[(size_t)(base + e) * T + tg] : 0.f;
            }
            __syncthreads();
        }
        const int xidx = t % XCH;
        const int nxt = cur ^ 1;

        // -------- output linear for step t-1 (overlaps L1 in phase 1) --------
        if (t > 0 && tid < E) {
            const ulonglong2* hv = (const ulonglong2*)&s->h2[cur][tid][0];
            const ulonglong2* wl = (const ulonglong2*)s->wlin;
            ull acc = pack2(s->blin, 0.f);
            #pragma unroll
            for (int k = 0; k < 14; k++) {
                ulonglong2 h = hv[k], w = wl[k];
                fma2(acc, h.x, w.x); fma2(acc, h.y, w.y);
            }
            float o = sum2(acc);
            out[(size_t)(base + tid) * TF + (t - 1)] = o;
            s->outp[tid] = o;
        }
        if (t >= T) __syncthreads();   // phase 2: outp feeds L1

        // ================= layer 1: 2 rows x 2 els x half-k =================
        {
            ull aR[2][2], aZ[2][2], aN[2][2];
            #pragma unroll
            for (int jj = 0; jj < 2; jj++)
                #pragma unroll
                for (int q = 0; q < 2; q++) {
                    aR[jj][q] = (kh == 0) ? pack2(s->bR1[j0 + jj], 0.f) : 0ull;
                    aZ[jj][q] = (kh == 0) ? pack2(s->bZ1[j0 + jj], 0.f) : 0ull;
                    aN[jj][q] = (kh == 0) ? pack2(s->bHN1[j0 + jj], 0.f) : 0ull;
                }
            const ulonglong2* pr = (const ulonglong2*)s->l1r + jg * 30 + kb;
            const ulonglong2* pz = (const ulonglong2*)s->l1z + jg * 30 + kb;
            const ulonglong2* pn = (const ulonglong2*)s->l1n + jg * 30 + kb;
            const ulonglong2* p0 = (const ulonglong2*)&s->h1[cur][e0][0] + kb;
            const ulonglong2* p1 = (const ulonglong2*)&s->h1[cur][e1][0] + kb;
            #pragma unroll
            for (int ki = 0; ki < 7; ki++) {
                ulonglong2 wR[2] = {pr[ki], pr[ki + 14]};
                ulonglong2 wZ[2] = {pz[ki], pz[ki + 14]};
                ulonglong2 wN[2] = {pn[ki], pn[ki + 14]};
                ulonglong2 hq[2] = {p0[ki], p1[ki]};
                #pragma unroll
                for (int jj = 0; jj < 2; jj++)
                    #pragma unroll
                    for (int q = 0; q < 2; q++) {
                        fma2(aR[jj][q], hq[q].x, wR[jj].x); fma2(aR[jj][q], hq[q].y, wR[jj].y);
                        fma2(aZ[jj][q], hq[q].x, wZ[jj].x); fma2(aZ[jj][q], hq[q].y, wZ[jj].y);
                        fma2(aN[jj][q], hq[q].x, wN[jj].x); fma2(aN[jj][q], hq[q].y, wN[jj].y);
                    }
            }
            float gR[2], gZ[2], gN[2];
            XRED(gR[0], gR[1], aR);
            XRED(gZ[0], gZ[1], aZ);
            XRED(gN[0], gN[1], aN);
            const float wr1 = s->wih1r[jme], wz1 = s->wih1z[jme];
            const float wn1 = s->wih1n[jme], bi  = s->bIN1[jme];
            #pragma unroll
            for (int q = 0; q < 2; q++) {
                int el = q ? e1 : e0;
                float xv = (t < T) ? s->xbuf[el][xidx] : s->outp[el];
                float ho = s->h1[cur][el][jme];
                s->h1[nxt][el][jme] = gru_cell(fmaf(xv, wr1, gR[q]), fmaf(xv, wz1, gZ[q]),
                                               fmaf(xv, wn1, bi), gN[q], ho);
            }
        }
        __syncthreads();

        // ================= layer 2: 2 rows x 2 els x half-k =================
        {
            ull aR[2][2], aZ[2][2], aI[2][2], aH[2][2];
            #pragma unroll
            for (int jj = 0; jj < 2; jj++)
                #pragma unroll
                for (int q = 0; q < 2; q++) {
                    aR[jj][q] = (kh == 0) ? pack2(s->bR2[j0 + jj], 0.f) : 0ull;
                    aZ[jj][q] = (kh == 0) ? pack2(s->bZ2[j0 + jj], 0.f) : 0ull;
                    aI[jj][q] = (kh == 0) ? pack2(s->bIN2[j0 + jj], 0.f) : 0ull;
                    aH[jj][q] = (kh == 0) ? pack2(s->bHN2[j0 + jj], 0.f) : 0ull;
                }
            const ulonglong2* pir = (const ulonglong2*)s->ir2 + jg * 30 + kb;
            const ulonglong2* piz = (const ulonglong2*)s->iz2 + jg * 30 + kb;
            const ulonglong2* pin = (const ulonglong2*)s->in2 + jg * 30 + kb;
            const ulonglong2* phr = (const ulonglong2*)s->hr2 + jg * 30 + kb;
            const ulonglong2* phz = (const ulonglong2*)s->hz2 + jg * 30 + kb;
            const ulonglong2* phn = (const ulonglong2*)s->hn2 + jg * 30 + kb;
            const ulonglong2* pu0 = (const ulonglong2*)&s->h1[nxt][e0][0] + kb;
            const ulonglong2* pu1 = (const ulonglong2*)&s->h1[nxt][e1][0] + kb;
            const ulonglong2* pv0 = (const ulonglong2*)&s->h2[cur][e0][0] + kb;
            const ulonglong2* pv1 = (const ulonglong2*)&s->h2[cur][e1][0] + kb;
            #pragma unroll
            for (int ki = 0; ki < 7; ki++) {
                ulonglong2 iR[2] = {pir[ki], pir[ki + 14]};
                ulonglong2 iZ[2] = {piz[ki], piz[ki + 14]};
                ulonglong2 iN[2] = {pin[ki], pin[ki + 14]};
                ulonglong2 hR[2] = {phr[ki], phr[ki + 14]};
                ulonglong2 hZ[2] = {phz[ki], phz[ki + 14]};
                ulonglong2 hN[2] = {phn[ki], phn[ki + 14]};
                ulonglong2 hu[2] = {pu0[ki], pu1[ki]};
                ulonglong2 hv[2] = {pv0[ki], pv1[ki]};
                #pragma unroll
                for (int jj = 0; jj < 2; jj++)
                    #pragma unroll
                    for (int q = 0; q < 2; q++) {
                        fma2(aR[jj][q], hu[q].x, iR[jj].x); fma2(aR[jj][q], hu[q].y, iR[jj].y);
                        fma2(aR[jj][q], hv[q].x, hR[jj].x); fma2(aR[jj][q], hv[q].y, hR[jj].y);
                        fma2(aZ[jj][q], hu[q].x, iZ[jj].x); fma2(aZ[jj][q], hu[q].y, iZ[jj].y);
                        fma2(aZ[jj][q], hv[q].x, hZ[jj].x); fma2(aZ[jj][q], hv[q].y, hZ[jj].y);
                        fma2(aI[jj][q], hu[q].x, iN[jj].x); fma2(aI[jj][q], hu[q].y, iN[jj].y);
                        fma2(aH[jj][q], hv[q].x, hN[jj].x); fma2(aH[jj][q], hv[q].y, hN[jj].y);
                    }
            }
            float gR[2], gZ[2], gI[2], gH[2];
            XRED(gR[0], gR[1], aR);
            XRED(gZ[0], gZ[1], aZ);
            XRED(gI[0], gI[1], aI);
            XRED(gH[0], gH[1], aH);
            #pragma unroll
            for (int q = 0; q < 2; q++) {
                int el = q ? e1 : e0;
                float ho = s->h2[cur][el][jme];
                s->h2[nxt][el][jme] = gru_cell(gR[q], gZ[q], gI[q], gH[q], ho);
            }
        }
        __syncthreads();

        cur = nxt;
    }

    // final output (step TF-1)
    if (tid < E) {
        const ulonglong2* hv = (const ulonglong2*)&s->h2[cur][tid][0];
        const ulonglong2* wl = (const ulonglong2*)s->wlin;
        ull acc = pack2(s->blin, 0.f);
        #pragma unroll
        for (int k = 0; k < 14; k++) {
            ulonglong2 h = hv[k], w = wl[k];
            fma2(acc, h.x, w.x); fma2(acc, h.y, w.y);
        }
        out[(size_t)(base + tid) * TF + (TF - 1)] = sum2(acc);
    }
}

extern "C" void kernel_launch(void* const* d_in, const int* in_sizes, int n_in,
                              void* d_out, int out_size)
{
    const float* x     = (const float*)d_in[0];
    const float* w_ih1 = (const float*)d_in[1];
    const float* w_hh1 = (const float*)d_in[2];
    const float* b_ih1 = (const float*)d_in[3];
    const float* b_hh1 = (const float*)d_in[4];
    const float* w_ih2 = (const float*)d_in[5];
    const float* w_hh2 = (const float*)d_in[6];
    const float* b_ih2 = (const float*)d_in[7];
    const float* b_hh2 = (const float*)d_in[8];
    const float* w_lin = (const float*)d_in[9];
    const float* b_lin = (const float*)d_in[10];

    const int B  = B_TOT;
    const int T  = in_sizes[0] / B;
    const int TF = out_size / B;
    const int F  = TF - T;

    size_t shmem = sizeof(Smem);
    cudaFuncSetAttribute(gru_stack_kernel,
                         cudaFuncAttributeMaxDynamicSharedMemorySize, (int)shmem);

    gru_stack_kernel<<<B / E, TPB, shmem>>>(
        x, w_ih1, w_hh1, b_ih1, b_hh1,
        w_ih2, w_hh2, b_ih2, b_hh2,
        w_lin, b_lin, (float*)d_out, T, F);
}

// round 9
// speedup vs baseline: 1.8773x; 1.8773x over previous
#include <cuda_runtime.h>

#define H     51
#define NJG   26          // j row-pair groups (52 rows, row 51 = zeros)
#define PAIRF 176         // floats per row-pair (2*80 + 16 pad) -> 44 u2 == 4 mod 8
#define QF    20          // floats per k-quarter slot (14 data + 6 pad) -> 5 u2
#define HROW  80          // floats per state vector (4 quarters)
#define WMAT  (NJG*PAIRF) // 4576 floats per gate matrix
#define E     16
#define TPB   416         // kq(4) * eg(4) * jg(26)
#define XCH   40
#define B_TOT 2048

typedef unsigned long long ull;

struct __align__(16) Smem {
    float l1r[WMAT], l1z[WMAT], l1n[WMAT];   // w_hh1 gates
    float ir2[WMAT], iz2[WMAT], in2[WMAT];   // w_ih2 gates
    float hr2[WMAT], hz2[WMAT], hn2[WMAT];   // w_hh2 gates
    float wih1r[52], wih1z[52], wih1n[52];
    float bR1[52], bZ1[52], bIN1[52], bHN1[52];
    float bR2[52], bZ2[52], bIN2[52], bHN2[52];
    float wlinP[HROW];                        // quarter-padded, pads 0
    float h1[2][E][HROW];                     // ping-pong, pads stay 0
    float h2[2][E][HROW];
    float xbuf[E][XCH];
    float outp[E];
    float blin;
};

__device__ __forceinline__ void fma2(ull& d, ull a, ull b) {
    asm("fma.rn.f32x2 %0, %1, %2, %0;" : "+l"(d) : "l"(a), "l"(b));
}
__device__ __forceinline__ ull pack2(float a, float b) {
    ull r; asm("mov.b64 %0, {%1,%2};" : "=l"(r) : "f"(a), "f"(b)); return r;
}
__device__ __forceinline__ float sum2(ull v) {
    float a, b; asm("mov.b64 {%0,%1}, %2;" : "=f"(a), "=f"(b) : "l"(v));
    return a + b;
}
__device__ __forceinline__ float sigmoid_(float v) {
    return __fdividef(1.0f, 1.0f + __expf(-v));
}
__device__ __forceinline__ float tanh_(float v) {
    return __fdividef(2.0f, 1.0f + __expf(-2.0f * v)) - 1.0f;
}
__device__ __forceinline__ float gru_cell(float gr, float gz, float gin,
                                          float ghn, float ho) {
    float r = sigmoid_(gr);
    float z = sigmoid_(gz);
    float n = tanh_(fmaf(r, ghn, gin));
    return fmaf(z, ho - n, n);
}
// Hierarchical ownership reduction over a [2(jj)][4(ei)] accumulator array.
// Stage 1 (xor 1): lane keeps jj == c1 row, sums over k-half pair.
// Stage 2 (xor 2): lane keeps ei pair {2c2, 2c2+1}, sums over k halves.
// Result: G0,G1 = full sums for (row j0+c1, ei = 2c2 / 2c2+1).
#define XRED42(G0, G1, A)                                                    \
    {                                                                        \
        float _s00 = sum2(A[0][0]), _s01 = sum2(A[0][1]);                    \
        float _s02 = sum2(A[0][2]), _s03 = sum2(A[0][3]);                    \
        float _s10 = sum2(A[1][0]), _s11 = sum2(A[1][1]);                    \
        float _s12 = sum2(A[1][2]), _s13 = sum2(A[1][3]);                    \
        float _k0 = c1 ? _s10 : _s00, _k1 = c1 ? _s11 : _s01;                \
        float _k2 = c1 ? _s12 : _s02, _k3 = c1 ? _s13 : _s03;                \
        float _d0 = c1 ? _s00 : _s10, _d1 = c1 ? _s01 : _s11;                \
        float _d2 = c1 ? _s02 : _s12, _d3 = c1 ? _s03 : _s13;                \
        float _p0 = _k0 + __shfl_xor_sync(0xFFFFFFFFu, _d0, 1);              \
        float _p1 = _k1 + __shfl_xor_sync(0xFFFFFFFFu, _d1, 1);              \
        float _p2 = _k2 + __shfl_xor_sync(0xFFFFFFFFu, _d2, 1);              \
        float _p3 = _k3 + __shfl_xor_sync(0xFFFFFFFFu, _d3, 1);              \
        float _ka = c2 ? _p2 : _p0, _kb = c2 ? _p3 : _p1;                    \
        float _da = c2 ? _p0 : _p2, _db = c2 ? _p1 : _p3;                    \
        G0 = _ka + __shfl_xor_sync(0xFFFFFFFFu, _da, 2);                     \
        G1 = _kb + __shfl_xor_sync(0xFFFFFFFFu, _db, 2);                     \
    }

__global__ void __launch_bounds__(TPB, 1) gru_stack_kernel(
    const float* __restrict__ x,
    const float* __restrict__ w_ih1, const float* __restrict__ w_hh1,
    const float* __restrict__ b_ih1, const float* __restrict__ b_hh1,
    const float* __restrict__ w_ih2, const float* __restrict__ w_hh2,
    const float* __restrict__ b_ih2, const float* __restrict__ b_hh2,
    const float* __restrict__ w_lin, const float* __restrict__ b_lin,
    float* __restrict__ out, int T, int F)
{
    extern __shared__ float smem_f[];
    Smem* s = reinterpret_cast<Smem*>(smem_f);

    const int tid = threadIdx.x;
    const int kq  = tid & 3;
    const int eg  = (tid >> 2) & 3;
    const int jg  = tid >> 4;               // 0..25
    const int c1  = kq & 1;
    const int c2  = (kq >> 1) & 1;
    const int j0  = 2 * jg;
    const int jme = j0 + c1;                // finalized gate row
    const int e0  = eg + 8 * c2;            // finalized elements e0, e0+4
    const int e1  = e0 + 4;
    const int pj  = (jme / 14) * QF + (jme % 14);  // h position of row jme
    const int base = blockIdx.x * E;
    const int TF   = T + F;

    // ---------------- one-time init ----------------
    for (int idx = tid; idx < WMAT; idx += TPB) {
        int jgx = idx / PAIRF, r = idx - jgx * PAIRF;
        int jj = r / HROW;                  // 0,1, or 2 (pair pad)
        int w  = r - jj * HROW;
        int q  = w / QF, i = w - q * QF;
        int j  = 2 * jgx + jj, k = q * 14 + i;
        bool valid = (jj < 2) && (i < 14) && (k < H) && (j < H);
        int o0 = valid ? (j * H + k) : 0;
        s->l1r[idx] = valid ? w_hh1[o0] : 0.f;
        s->l1z[idx] = valid ? w_hh1[(H * H) + o0] : 0.f;
        s->l1n[idx] = valid ? w_hh1[(2 * H * H) + o0] : 0.f;
        s->ir2[idx] = valid ? w_ih2[o0] : 0.f;
        s->iz2[idx] = valid ? w_ih2[(H * H) + o0] : 0.f;
        s->in2[idx] = valid ? w_ih2[(2 * H * H) + o0] : 0.f;
        s->hr2[idx] = valid ? w_hh2[o0] : 0.f;
        s->hz2[idx] = valid ? w_hh2[(H * H) + o0] : 0.f;
        s->hn2[idx] = valid ? w_hh2[(2 * H * H) + o0] : 0.f;
    }
    for (int i = tid; i < 52; i += TPB) {
        bool v = (i < H);
        s->wih1r[i] = v ? w_ih1[i] : 0.f;
        s->wih1z[i] = v ? w_ih1[H + i] : 0.f;
        s->wih1n[i] = v ? w_ih1[2 * H + i] : 0.f;
        s->bR1[i]  = v ? (b_ih1[i] + b_hh1[i]) : 0.f;
        s->bZ1[i]  = v ? (b_ih1[H + i] + b_hh1[H + i]) : 0.f;
        s->bIN1[i] = v ? b_ih1[2 * H + i] : 0.f;
        s->bHN1[i] = v ? b_hh1[2 * H + i] : 0.f;
        s->bR2[i]  = v ? (b_ih2[i] + b_hh2[i]) : 0.f;
        s->bZ2[i]  = v ? (b_ih2[H + i] + b_hh2[H + i]) : 0.f;
        s->bIN2[i] = v ? b_ih2[2 * H + i] : 0.f;
        s->bHN2[i] = v ? b_hh2[2 * H + i] : 0.f;
    }
    for (int i = tid; i < HROW; i += TPB) {
        int q = i / QF, ii = i - q * QF, k = q * 14 + ii;
        s->wlinP[i] = (ii < 14 && k < H) ? w_lin[k] : 0.f;
    }
    if (tid == 0) s->blin = b_lin[0];
    {
        float* h1f = &s->h1[0][0][0];
        float* h2f = &s->h2[0][0][0];
        for (int i = tid; i < 2 * E * HROW; i += TPB) { h1f[i] = 0.f; h2f[i] = 0.f; }
        for (int i = tid; i < E; i += TPB) s->outp[i] = 0.f;
    }
    __syncthreads();

    int cur = 0;
    for (int t = 0; t < TF; ++t) {
        const int nxt = cur ^ 1;
        if (t < T && (t % XCH) == 0) {
            for (int i = tid; i < E * XCH; i += TPB) {
                int e = i / XCH, c = i - e * XCH;
                int tg = t + c;
                s->xbuf[e][c] = (tg < T) ? x[(size_t)(base + e) * T + tg] : 0.f;
            }
            __syncthreads();
        }
        const int xidx = t % XCH;

        // -------- output linear for step t-1 (overlaps L1 in phase 1) --------
        if (t > 0 && tid < E) {
            const ulonglong2* hv = (const ulonglong2*)&s->h2[cur][tid][0];
            const ulonglong2* wl = (const ulonglong2*)s->wlinP;
            ull acc = pack2(s->blin, 0.f);
            #pragma unroll
            for (int k = 0; k < HROW / 4; k++) {
                ulonglong2 h = hv[k], w = wl[k];
                fma2(acc, h.x, w.x); fma2(acc, h.y, w.y);
            }
            float o = sum2(acc);
            out[(size_t)(base + tid) * TF + (t - 1)] = o;
            s->outp[tid] = o;
        }
        if (t >= T) __syncthreads();   // phase 2: outp feeds L1

        // ======================= layer 1 =======================
        {
            ull aR[2][4], aZ[2][4], aN[2][4];
            {
                float2 br = *(const float2*)&s->bR1[j0];
                float2 bz = *(const float2*)&s->bZ1[j0];
                float2 bn = *(const float2*)&s->bHN1[j0];
                #pragma unroll
                for (int ei = 0; ei < 4; ei++) {
                    aR[0][ei] = (kq == 0) ? pack2(br.x, 0.f) : 0ull;
                    aR[1][ei] = (kq == 0) ? pack2(br.y, 0.f) : 0ull;
                    aZ[0][ei] = (kq == 0) ? pack2(bz.x, 0.f) : 0ull;
                    aZ[1][ei] = (kq == 0) ? pack2(bz.y, 0.f) : 0ull;
                    aN[0][ei] = (kq == 0) ? pack2(bn.x, 0.f) : 0ull;
                    aN[1][ei] = (kq == 0) ? pack2(bn.y, 0.f) : 0ull;
                }
            }
            const float* wrB = s->l1r + jg * PAIRF + kq * QF;
            const float* wzB = s->l1z + jg * PAIRF + kq * QF;
            const float* wnB = s->l1n + jg * PAIRF + kq * QF;
            const float* hB  = &s->h1[cur][0][0] + eg * HROW + kq * QF;
            #pragma unroll
            for (int ki = 0; ki < 3; ki++) {
                ulonglong2 r0 = ((const ulonglong2*)wrB)[ki];
                ulonglong2 r1 = ((const ulonglong2*)(wrB + HROW))[ki];
                ulonglong2 z0 = ((const ulonglong2*)wzB)[ki];
                ulonglong2 z1 = ((const ulonglong2*)(wzB + HROW))[ki];
                ulonglong2 n0 = ((const ulonglong2*)wnB)[ki];
                ulonglong2 n1 = ((const ulonglong2*)(wnB + HROW))[ki];
                #pragma unroll
                for (int ei = 0; ei < 4; ei++) {
                    ulonglong2 h = ((const ulonglong2*)(hB + ei * 4 * HROW))[ki];
                    fma2(aR[0][ei], h.x, r0.x); fma2(aR[0][ei], h.y, r0.y);
                    fma2(aR[1][ei], h.x, r1.x); fma2(aR[1][ei], h.y, r1.y);
                    fma2(aZ[0][ei], h.x, z0.x); fma2(aZ[0][ei], h.y, z0.y);
                    fma2(aZ[1][ei], h.x, z1.x); fma2(aZ[1][ei], h.y, z1.y);
                    fma2(aN[0][ei], h.x, n0.x); fma2(aN[0][ei], h.y, n0.y);
                    fma2(aN[1][ei], h.x, n1.x); fma2(aN[1][ei], h.y, n1.y);
                }
            }
            {   // tail: floats 12,13 of the quarter
                ull r0 = *(const ull*)(wrB + 12), r1 = *(const ull*)(wrB + HROW + 12);
                ull z0 = *(const ull*)(wzB + 12), z1 = *(const ull*)(wzB + HROW + 12);
                ull n0 = *(const ull*)(wnB + 12), n1 = *(const ull*)(wnB + HROW + 12);
                #pragma unroll
                for (int ei = 0; ei < 4; ei++) {
                    ull h = *(const ull*)(hB + ei * 4 * HROW + 12);
                    fma2(aR[0][ei], h, r0); fma2(aR[1][ei], h, r1);
                    fma2(aZ[0][ei], h, z0); fma2(aZ[1][ei], h, z1);
                    fma2(aN[0][ei], h, n0); fma2(aN[1][ei], h, n1);
                }
            }
            float gR0, gR1, gZ0, gZ1, gN0, gN1;
            XRED42(gR0, gR1, aR);
            XRED42(gZ0, gZ1, aZ);
            XRED42(gN0, gN1, aN);

            const float wr1 = s->wih1r[jme], wz1 = s->wih1z[jme];
            const float wn1 = s->wih1n[jme], bi  = s->bIN1[jme];
            {
                float xv = (t < T) ? s->xbuf[e0][xidx] : s->outp[e0];
                float ho = s->h1[cur][e0][pj];
                s->h1[nxt][e0][pj] = gru_cell(fmaf(xv, wr1, gR0), fmaf(xv, wz1, gZ0),
                                              fmaf(xv, wn1, bi), gN0, ho);
            }
            {
                float xv = (t < T) ? s->xbuf[e1][xidx] : s->outp[e1];
                float ho = s->h1[cur][e1][pj];
                s->h1[nxt][e1][pj] = gru_cell(fmaf(xv, wr1, gR1), fmaf(xv, wz1, gZ1),
                                              fmaf(xv, wn1, bi), gN1, ho);
            }
        }
        __syncthreads();

        // ======================= layer 2 =======================
        {
            const float* uB = &s->h1[nxt][0][0] + eg * HROW + kq * QF;
            const float* vB = &s->h2[cur][0][0] + eg * HROW + kq * QF;
            float gR0, gR1, gZ0, gZ1;
            {   // ---- pass RZ ----
                ull aR[2][4], aZ[2][4];
                float2 br = *(const float2*)&s->bR2[j0];
                float2 bz = *(const float2*)&s->bZ2[j0];
                #pragma unroll
                for (int ei = 0; ei < 4; ei++) {
                    aR[0][ei] = (kq == 0) ? pack2(br.x, 0.f) : 0ull;
                    aR[1][ei] = (kq == 0) ? pack2(br.y, 0.f) : 0ull;
                    aZ[0][ei] = (kq == 0) ? pack2(bz.x, 0.f) : 0ull;
                    aZ[1][ei] = (kq == 0) ? pack2(bz.y, 0.f) : 0ull;
                }
                const float* irB = s->ir2 + jg * PAIRF + kq * QF;
                const float* izB = s->iz2 + jg * PAIRF + kq * QF;
                const float* hrB = s->hr2 + jg * PAIRF + kq * QF;
                const float* hzB = s->hz2 + jg * PAIRF + kq * QF;
                #pragma unroll
                for (int ki = 0; ki < 3; ki++) {
                    ulonglong2 i0 = ((const ulonglong2*)irB)[ki];
                    ulonglong2 i1 = ((const ulonglong2*)(irB + HROW))[ki];
                    ulonglong2 z0 = ((const ulonglong2*)izB)[ki];
                    ulonglong2 z1 = ((const ulonglong2*)(izB + HROW))[ki];
                    ulonglong2 p0 = ((const ulonglong2*)hrB)[ki];
                    ulonglong2 p1 = ((const ulonglong2*)(hrB + HROW))[ki];
                    ulonglong2 q0 = ((const ulonglong2*)hzB)[ki];
                    ulonglong2 q1 = ((const ulonglong2*)(hzB + HROW))[ki];
                    #pragma unroll
                    for (int ei = 0; ei < 4; ei++) {
                        ulonglong2 u = ((const ulonglong2*)(uB + ei * 4 * HROW))[ki];
                        ulonglong2 v = ((const ulonglong2*)(vB + ei * 4 * HROW))[ki];
                        fma2(aR[0][ei], u.x, i0.x); fma2(aR[0][ei], u.y, i0.y);
                        fma2(aR[0][ei], v.x, p0.x); fma2(aR[0][ei], v.y, p0.y);
                        fma2(aR[1][ei], u.x, i1.x); fma2(aR[1][ei], u.y, i1.y);
                        fma2(aR[1][ei], v.x, p1.x); fma2(aR[1][ei], v.y, p1.y);
                        fma2(aZ[0][ei], u.x, z0.x); fma2(aZ[0][ei], u.y, z0.y);
                        fma2(aZ[0][ei], v.x, q0.x); fma2(aZ[0][ei], v.y, q0.y);
                        fma2(aZ[1][ei], u.x, z1.x); fma2(aZ[1][ei], u.y, z1.y);
                        fma2(aZ[1][ei], v.x, q1.x); fma2(aZ[1][ei], v.y, q1.y);
                    }
                }
                {
                    ull i0 = *(const ull*)(irB + 12), i1 = *(const ull*)(irB + HROW + 12);
                    ull z0 = *(const ull*)(izB + 12), z1 = *(const ull*)(izB + HROW + 12);
                    ull p0 = *(const ull*)(hrB + 12), p1 = *(const ull*)(hrB + HROW + 12);
                    ull q0 = *(const ull*)(hzB + 12), q1 = *(const ull*)(hzB + HROW + 12);
                    #pragma unroll
                    for (int ei = 0; ei < 4; ei++) {
                        ull u = *(const ull*)(uB + ei * 4 * HROW + 12);
                        ull v = *(const ull*)(vB + ei * 4 * HROW + 12);
                        fma2(aR[0][ei], u, i0); fma2(aR[0][ei], v, p0);
                        fma2(aR[1][ei], u, i1); fma2(aR[1][ei], v, p1);
                        fma2(aZ[0][ei], u, z0); fma2(aZ[0][ei], v, q0);
                        fma2(aZ[1][ei], u, z1); fma2(aZ[1][ei], v, q1);
                    }
                }
                XRED42(gR0, gR1, aR);
                XRED42(gZ0, gZ1, aZ);
            }
            float gI0, gI1, gH0, gH1;
            {   // ---- pass N ----
                ull aI[2][4], aH[2][4];
                float2 bi = *(const float2*)&s->bIN2[j0];
                float2 bh = *(const float2*)&s->bHN2[j0];
                #pragma unroll
                for (int ei = 0; ei < 4; ei++) {
                    aI[0][ei] = (kq == 0) ? pack2(bi.x, 0.f) : 0ull;
                    aI[1][ei] = (kq == 0) ? pack2(bi.y, 0.f) : 0ull;
                    aH[0][ei] = (kq == 0) ? pack2(bh.x, 0.f) : 0ull;
                    aH[1][ei] = (kq == 0) ? pack2(bh.y, 0.f) : 0ull;
                }
                const float* inB = s->in2 + jg * PAIRF + kq * QF;
                const float* hnB = s->hn2 + jg * PAIRF + kq * QF;
                #pragma unroll
                for (int ki = 0; ki < 3; ki++) {
                    ulonglong2 n0 = ((const ulonglong2*)inB)[ki];
                    ulonglong2 n1 = ((const ulonglong2*)(inB + HROW))[ki];
                    ulonglong2 m0 = ((const ulonglong2*)hnB)[ki];
                    ulonglong2 m1 = ((const ulonglong2*)(hnB + HROW))[ki];
                    #pragma unroll
                    for (int ei = 0; ei < 4; ei++) {
                        ulonglong2 u = ((const ulonglong2*)(uB + ei * 4 * HROW))[ki];
                        ulonglong2 v = ((const ulonglong2*)(vB + ei * 4 * HROW))[ki];
                        fma2(aI[0][ei], u.x, n0.x); fma2(aI[0][ei], u.y, n0.y);
                        fma2(aI[1][ei], u.x, n1.x); fma2(aI[1][ei], u.y, n1.y);
                        fma2(aH[0][ei], v.x, m0.x); fma2(aH[0][ei], v.y, m0.y);
                        fma2(aH[1][ei], v.x, m1.x); fma2(aH[1][ei], v.y, m1.y);
                    }
                }
                {
                    ull n0 = *(const ull*)(inB + 12), n1 = *(const ull*)(inB + HROW + 12);
                    ull m0 = *(const ull*)(hnB + 12), m1 = *(const ull*)(hnB + HROW + 12);
                    #pragma unroll
                    for (int ei = 0; ei < 4; ei++) {
                        ull u = *(const ull*)(uB + ei * 4 * HROW + 12);
                        ull v = *(const ull*)(vB + ei * 4 * HROW + 12);
                        fma2(aI[0][ei], u, n0); fma2(aI[1][ei], u, n1);
                        fma2(aH[0][ei], v, m0); fma2(aH[1][ei], v, m1);
                    }
                }
                XRED42(gI0, gI1, aI);
                XRED42(gH0, gH1, aH);
            }
            {
                float ho = s->h2[cur][e0][pj];
                s->h2[nxt][e0][pj] = gru_cell(gR0, gZ0, gI0, gH0, ho);
            }
            {
                float ho = s->h2[cur][e1][pj];
                s->h2[nxt][e1][pj] = gru_cell(gR1, gZ1, gI1, gH1, ho);
            }
        }
        __syncthreads();

        cur = nxt;
    }

    // final output (step TF-1)
    if (tid < E) {
        const ulonglong2* hv = (const ulonglong2*)&s->h2[cur][tid][0];
        const ulonglong2* wl = (const ulonglong2*)s->wlinP;
        ull acc = pack2(s->blin, 0.f);
        #pragma unroll
        for (int k = 0; k < HROW / 4; k++) {
            ulonglong2 h = hv[k], w = wl[k];
            fma2(acc, h.x, w.x); fma2(acc, h.y, w.y);
        }
        out[(size_t)(base + tid) * TF + (TF - 1)] = sum2(acc);
    }
}

extern "C" void kernel_launch(void* const* d_in, const int* in_sizes, int n_in,
                              void* d_out, int out_size)
{
    const float* x     = (const float*)d_in[0];
    const float* w_ih1 = (const float*)d_in[1];
    const float* w_hh1 = (const float*)d_in[2];
    const float* b_ih1 = (const float*)d_in[3];
    const float* b_hh1 = (const float*)d_in[4];
    const float* w_ih2 = (const float*)d_in[5];
    const float* w_hh2 = (const float*)d_in[6];
    const float* b_ih2 = (const float*)d_in[7];
    const float* b_hh2 = (const float*)d_in[8];
    const float* w_lin = (const float*)d_in[9];
    const float* b_lin = (const float*)d_in[10];

    const int B  = B_TOT;
    const int T  = in_sizes[0] / B;
    const int TF = out_size / B;
    const int F  = TF - T;

    size_t shmem = sizeof(Smem);
    cudaFuncSetAttribute(gru_stack_kernel,
                         cudaFuncAttributeMaxDynamicSharedMemorySize, (int)shmem);

    gru_stack_kernel<<<B / E, TPB, shmem>>>(
        x, w_ih1, w_hh1, b_ih1, b_hh1,
        w_ih2, w_hh2, b_ih2, b_hh2,
        w_lin, b_lin, (float*)d_out, T, F);
}

// round 10
// speedup vs baseline: 2.3069x; 1.2288x over previous
#include <cuda_runtime.h>

#define B_TOT 2048
#define H     51
#define HP    52           // padded gate rows (row 51 = zeros)
#define KP    56           // padded k stride per row (floats)
#define KU2   14           // KP in ulonglong2 units
#define PAIR  120          // floats per j-row-pair (2*56 + 8 pad)
#define NJG   26           // j-row-pair groups (covers 52 rows)
#define WSZ   (NJG*PAIR)   // floats per padded gate matrix = 3120
#define E     16           // elements per block
#define TPB   256          // 8 warps -> 2/2/2/2 per SMSP; tids >= 208 clone jg=25
#define XCH   40

typedef unsigned long long ull;

struct __align__(16) Smem {
    // padded gate matrices: row j at (j>>1)*PAIR + (j&1)*KP
    float l1r[WSZ], l1z[WSZ], l1n[WSZ];      // w_hh1
    float ir2[WSZ], iz2[WSZ], in2[WSZ];      // w_ih2
    float hr2[WSZ], hz2[WSZ], hn2[WSZ];      // w_hh2
    float wih1r[HP], wih1z[HP], wih1n[HP];   // w_ih1 columns (input dim 1)
    float bR1[HP], bZ1[HP], bIN1[HP], bHN1[HP];
    float bR2[HP], bZ2[HP], bIN2[HP], bHN2[HP];
    float wlin[KP];
    float h1[2][E][KP];                      // ping-pong, pads stay 0
    float h2[2][E][KP];
    float xbuf[E][XCH];
    float outp[E];
    float blin;
};

__device__ __forceinline__ void fma2(ull& d, ull a, ull b) {
    asm("fma.rn.f32x2 %0, %1, %2, %0;" : "+l"(d) : "l"(a), "l"(b));
}
__device__ __forceinline__ ull pack2(float a, float b) {
    ull r; asm("mov.b64 %0, {%1,%2};" : "=l"(r) : "f"(a), "f"(b)); return r;
}
__device__ __forceinline__ float sum2(ull v) {
    float a, b; asm("mov.b64 {%0,%1}, %2;" : "=f"(a), "=f"(b) : "l"(v));
    return a + b;
}
__device__ __forceinline__ float sigmoid_(float v) {
    return __fdividef(1.0f, 1.0f + __expf(-v));
}
__device__ __forceinline__ float tanh_(float v) {
    return __fdividef(2.0f, 1.0f + __expf(-2.0f * v)) - 1.0f;
}
__device__ __forceinline__ float gru_cell(float gr, float gz, float gin,
                                          float ghn, float ho) {
    float r = sigmoid_(gr);
    float z = sigmoid_(gz);
    float n = tanh_(fmaf(r, ghn, gin));
    return fmaf(z, ho - n, n);
}
// lane kh keeps jj=kh partial, receives partner's jj=kh partial (1 float shfl)
__device__ __forceinline__ float xred(ull a0, ull a1, int kh) {
    ull keep = kh ? a1 : a0;
    ull send = kh ? a0 : a1;
    float sf = sum2(send);
    return sum2(keep) + __shfl_xor_sync(0xFFFFFFFFu, sf, 1);
}

// fill one padded gate matrix (gate g of a [153][51] row-major source)
__device__ __forceinline__ void fill_mat(float* dst, const float* src, int g, int tid) {
    for (int idx = tid; idx < WSZ; idx += TPB) {
        int jg = idx / PAIR, rem = idx - jg * PAIR;
        int jj = rem / KP;                  // 0,1, or 2 => inter-pair pad
        int k  = rem - jj * KP;
        float v = 0.f;
        if (jj < 2) {
            int j = jg * 2 + jj;
            if (j < H && k < H) v = src[(g * H + j) * H + k];
        }
        dst[idx] = v;
    }
}

__global__ void __launch_bounds__(TPB, 1) gru_stack_kernel(
    const float* __restrict__ x,
    const float* __restrict__ w_ih1, const float* __restrict__ w_hh1,
    const float* __restrict__ b_ih1, const float* __restrict__ b_hh1,
    const float* __restrict__ w_ih2, const float* __restrict__ w_hh2,
    const float* __restrict__ b_ih2, const float* __restrict__ b_hh2,
    const float* __restrict__ w_lin, const float* __restrict__ b_lin,
    float* __restrict__ out, int T, int F)
{
    extern __shared__ float smem_f[];
    Smem* s = reinterpret_cast<Smem*>(smem_f);

    const int tid = threadIdx.x;
    const int kh  = tid & 1;                 // k-half, also owned jj
    const int eg  = (tid >> 1) & 3;          // element group: el = eg + 4*ei
    int jgt = tid >> 3; if (jgt > NJG - 1) jgt = NJG - 1;   // clone tail threads
    const int jg  = jgt;
    const int j0  = 2 * jg;
    const int jme = j0 + kh;                 // the gate row this lane finalizes
    const int kb  = kh * (KU2 / 2);          // k-half offset in u2 units (7)
    const bool isOut = (tid >= 240);         // clone warp lanes own the out-linear
    const int  elo   = tid - 240;
    const int base = blockIdx.x * E;
    const int TF   = T + F;

    // ---------------- one-time init ----------------
    fill_mat(s->l1r, w_hh1, 0, tid); fill_mat(s->l1z, w_hh1, 1, tid); fill_mat(s->l1n, w_hh1, 2, tid);
    fill_mat(s->ir2, w_ih2, 0, tid); fill_mat(s->iz2, w_ih2, 1, tid); fill_mat(s->in2, w_ih2, 2, tid);
    fill_mat(s->hr2, w_hh2, 0, tid); fill_mat(s->hz2, w_hh2, 1, tid); fill_mat(s->hn2, w_hh2, 2, tid);
    for (int i = tid; i < HP; i += TPB) {
        bool v = (i < H);
        s->wih1r[i] = v ? w_ih1[i] : 0.f;
        s->wih1z[i] = v ? w_ih1[H + i] : 0.f;
        s->wih1n[i] = v ? w_ih1[2 * H + i] : 0.f;
        s->bR1[i]  = v ? (b_ih1[i] + b_hh1[i]) : 0.f;
        s->bZ1[i]  = v ? (b_ih1[H + i] + b_hh1[H + i]) : 0.f;
        s->bIN1[i] = v ? b_ih1[2 * H + i] : 0.f;
        s->bHN1[i] = v ? b_hh1[2 * H + i] : 0.f;
        s->bR2[i]  = v ? (b_ih2[i] + b_hh2[i]) : 0.f;
        s->bZ2[i]  = v ? (b_ih2[H + i] + b_hh2[H + i]) : 0.f;
        s->bIN2[i] = v ? b_ih2[2 * H + i] : 0.f;
        s->bHN2[i] = v ? b_hh2[2 * H + i] : 0.f;
    }
    for (int i = tid; i < KP; i += TPB) s->wlin[i] = (i < H) ? w_lin[i] : 0.f;
    if (tid == 0) s->blin = b_lin[0];
    {
        float* h1f = &s->h1[0][0][0];
        float* h2f = &s->h2[0][0][0];
        for (int i = tid; i < 2 * E * KP; i += TPB) { h1f[i] = 0.f; h2f[i] = 0.f; }
        for (int i = tid; i < E; i += TPB) s->outp[i] = 0.f;
    }
    __syncthreads();

    int cur = 0;
    for (int t = 0; t < TF; ++t) {
        if (t < T && (t % XCH) == 0) {
            for (int i = tid; i < E * XCH; i += TPB) {
                int e = i / XCH, c = i - e * XCH;
                int tg = t + c;
                s->xbuf[e][c] = (tg < T) ? x[(size_t)(base + e) * T + tg] : 0.f;
            }
            __syncthreads();
        }
        const int xidx = t % XCH;
        const int nxt = cur ^ 1;

        // -------- output linear for step t-1 (clone warp) --------
        if (t > 0 && isOut) {
            const ulonglong2* hv = (const ulonglong2*)&s->h2[cur][elo][0];
            const ulonglong2* wl = (const ulonglong2*)s->wlin;
            ull acc = pack2(s->blin, 0.f);
            #pragma unroll
            for (int k = 0; k < KU2; k++) {
                ulonglong2 h = hv[k], w = wl[k];
                fma2(acc, h.x, w.x); fma2(acc, h.y, w.y);
            }
            float o = sum2(acc);
            out[(size_t)(base + elo) * TF + (t - 1)] = o;
            s->outp[elo] = o;
        }
        if (t >= T) __syncthreads();   // phase 2: outp feeds L1

        // ================= layer 1: tile 2j x 4e, k-half =================
        {
            ull aR[2][4], aZ[2][4], aN[2][4];
            #pragma unroll
            for (int jj = 0; jj < 2; jj++)
                #pragma unroll
                for (int ei = 0; ei < 4; ei++) {
                    aR[jj][ei] = (kh == 0) ? pack2(s->bR1[j0 + jj], 0.f) : 0ull;
                    aZ[jj][ei] = (kh == 0) ? pack2(s->bZ1[j0 + jj], 0.f) : 0ull;
                    aN[jj][ei] = (kh == 0) ? pack2(s->bHN1[j0 + jj], 0.f) : 0ull;
                }
            const ulonglong2* pr = (const ulonglong2*)&s->l1r[jg * PAIR] + kb;
            const ulonglong2* pz = (const ulonglong2*)&s->l1z[jg * PAIR] + kb;
            const ulonglong2* pn = (const ulonglong2*)&s->l1n[jg * PAIR] + kb;
            const ulonglong2* ph = (const ulonglong2*)&s->h1[cur][0][0] + eg * KU2 + kb;
            #pragma unroll
            for (int ki = 0; ki < 7; ki++) {
                ulonglong2 w[6];
                w[0] = pr[ki]; w[1] = pr[ki + KU2];
                w[2] = pz[ki]; w[3] = pz[ki + KU2];
                w[4] = pn[ki]; w[5] = pn[ki + KU2];
                ulonglong2 hv[4];
                #pragma unroll
                for (int ei = 0; ei < 4; ei++) hv[ei] = ph[ki + ei * 4 * KU2];
                #pragma unroll
                for (int jj = 0; jj < 2; jj++)
                    #pragma unroll
                    for (int ei = 0; ei < 4; ei++) {
                        fma2(aR[jj][ei], hv[ei].x, w[0 + jj].x); fma2(aR[jj][ei], hv[ei].y, w[0 + jj].y);
                        fma2(aZ[jj][ei], hv[ei].x, w[2 + jj].x); fma2(aZ[jj][ei], hv[ei].y, w[2 + jj].y);
                        fma2(aN[jj][ei], hv[ei].x, w[4 + jj].x); fma2(aN[jj][ei], hv[ei].y, w[4 + jj].y);
                    }
            }
            // exchange partials: this lane finalizes row jme = j0 + kh only
            float gr[4], gz[4], gn[4];
            #pragma unroll
            for (int ei = 0; ei < 4; ei++) {
                gr[ei] = xred(aR[0][ei], aR[1][ei], kh);
                gz[ei] = xred(aZ[0][ei], aZ[1][ei], kh);
                gn[ei] = xred(aN[0][ei], aN[1][ei], kh);
            }
            const float wr1 = s->wih1r[jme], wz1 = s->wih1z[jme];
            const float wn1 = s->wih1n[jme], bi  = s->bIN1[jme];
            #pragma unroll
            for (int ei = 0; ei < 4; ei++) {
                int el = eg + 4 * ei;
                float xv = (t < T) ? s->xbuf[el][xidx] : s->outp[el];
                float ho = s->h1[cur][el][jme];
                float nh = gru_cell(fmaf(xv, wr1, gr[ei]), fmaf(xv, wz1, gz[ei]),
                                    fmaf(xv, wn1, bi), gn[ei], ho);
                s->h1[nxt][el][jme] = nh;
            }
        }
        __syncthreads();

        // ================= layer 2: tile 2j x 4e, k-half =================
        {
            ull aR[2][4], aZ[2][4], aI[2][4], aH[2][4];
            #pragma unroll
            for (int jj = 0; jj < 2; jj++)
                #pragma unroll
                for (int ei = 0; ei < 4; ei++) {
                    aR[jj][ei] = (kh == 0) ? pack2(s->bR2[j0 + jj], 0.f) : 0ull;
                    aZ[jj][ei] = (kh == 0) ? pack2(s->bZ2[j0 + jj], 0.f) : 0ull;
                    aI[jj][ei] = (kh == 0) ? pack2(s->bIN2[j0 + jj], 0.f) : 0ull;
                    aH[jj][ei] = (kh == 0) ? pack2(s->bHN2[j0 + jj], 0.f) : 0ull;
                }
            const ulonglong2* pir = (const ulonglong2*)&s->ir2[jg * PAIR] + kb;
            const ulonglong2* piz = (const ulonglong2*)&s->iz2[jg * PAIR] + kb;
            const ulonglong2* pin = (const ulonglong2*)&s->in2[jg * PAIR] + kb;
            const ulonglong2* phr = (const ulonglong2*)&s->hr2[jg * PAIR] + kb;
            const ulonglong2* phz = (const ulonglong2*)&s->hz2[jg * PAIR] + kb;
            const ulonglong2* phn = (const ulonglong2*)&s->hn2[jg * PAIR] + kb;
            const ulonglong2* pu  = (const ulonglong2*)&s->h1[nxt][0][0] + eg * KU2 + kb;
            const ulonglong2* pv  = (const ulonglong2*)&s->h2[cur][0][0] + eg * KU2 + kb;
            #pragma unroll
            for (int ki = 0; ki < 7; ki++) {
                ulonglong2 wi[6], wh[6];
                wi[0] = pir[ki]; wi[1] = pir[ki + KU2];
                wi[2] = piz[ki]; wi[3] = piz[ki + KU2];
                wi[4] = pin[ki]; wi[5] = pin[ki + KU2];
                wh[0] = phr[ki]; wh[1] = phr[ki + KU2];
                wh[2] = phz[ki]; wh[3] = phz[ki + KU2];
                wh[4] = phn[ki]; wh[5] = phn[ki + KU2];
                ulonglong2 uv[4], vv[4];
                #pragma unroll
                for (int ei = 0; ei < 4; ei++) {
                    uv[ei] = pu[ki + ei * 4 * KU2];
                    vv[ei] = pv[ki + ei * 4 * KU2];
                }
                #pragma unroll
                for (int jj = 0; jj < 2; jj++)
                    #pragma unroll
                    for (int ei = 0; ei < 4; ei++) {
                        fma2(aR[jj][ei], uv[ei].x, wi[0 + jj].x); fma2(aR[jj][ei], uv[ei].y, wi[0 + jj].y);
                        fma2(aR[jj][ei], vv[ei].x, wh[0 + jj].x); fma2(aR[jj][ei], vv[ei].y, wh[0 + jj].y);
                        fma2(aZ[jj][ei], uv[ei].x, wi[2 + jj].x); fma2(aZ[jj][ei], uv[ei].y, wi[2 + jj].y);
                        fma2(aZ[jj][ei], vv[ei].x, wh[2 + jj].x); fma2(aZ[jj][ei], vv[ei].y, wh[2 + jj].y);
                        fma2(aI[jj][ei], uv[ei].x, wi[4 + jj].x); fma2(aI[jj][ei], uv[ei].y, wi[4 + jj].y);
                        fma2(aH[jj][ei], vv[ei].x, wh[4 + jj].x); fma2(aH[jj][ei], vv[ei].y, wh[4 + jj].y);
                    }
            }
            float gr[4], gz[4], gi[4], gh[4];
            #pragma unroll
            for (int ei = 0; ei < 4; ei++) {
                gr[ei] = xred(aR[0][ei], aR[1][ei], kh);
                gz[ei] = xred(aZ[0][ei], aZ[1][ei], kh);
                gi[ei] = xred(aI[0][ei], aI[1][ei], kh);
                gh[ei] = xred(aH[0][ei], aH[1][ei], kh);
            }
            #pragma unroll
            for (int ei = 0; ei < 4; ei++) {
                int el = eg + 4 * ei;
                float ho = s->h2[cur][el][jme];
                float nh = gru_cell(gr[ei], gz[ei], gi[ei], gh[ei], ho);
                s->h2[nxt][el][jme] = nh;
            }
        }
        __syncthreads();

        cur = nxt;
    }

    // final output (step TF-1)
    if (isOut) {
        const ulonglong2* hv = (const ulonglong2*)&s->h2[cur][elo][0];
        const ulonglong2* wl = (const ulonglong2*)s->wlin;
        ull acc = pack2(s->blin, 0.f);
        #pragma unroll
        for (int k = 0; k < KU2; k++) {
            ulonglong2 h = hv[k], w = wl[k];
            fma2(acc, h.x, w.x); fma2(acc, h.y, w.y);
        }
        out[(size_t)(base + elo) * TF + (TF - 1)] = sum2(acc);
    }
}

extern "C" void kernel_launch(void* const* d_in, const int* in_sizes, int n_in,
                              void* d_out, int out_size)
{
    const float* x     = (const float*)d_in[0];
    const float* w_ih1 = (const float*)d_in[1];
    const float* w_hh1 = (const float*)d_in[2];
    const float* b_ih1 = (const float*)d_in[3];
    const float* b_hh1 = (const float*)d_in[4];
    const float* w_ih2 = (const float*)d_in[5];
    const float* w_hh2 = (const float*)d_in[6];
    const float* b_ih2 = (const float*)d_in[7];
    const float* b_hh2 = (const float*)d_in[8];
    const float* w_lin = (const float*)d_in[9];
    const float* b_lin = (const float*)d_in[10];

    const int B  = B_TOT;
    const int T  = in_sizes[0] / B;
    const int TF = out_size / B;
    const int F  = TF - T;

    size_t shmem = sizeof(Smem);
    cudaFuncSetAttribute(gru_stack_kernel,
                         cudaFuncAttributeMaxDynamicSharedMemorySize, (int)shmem);

    gru_stack_kernel<<<B / E, TPB, shmem>>>(
        x, w_ih1, w_hh1, b_ih1, b_hh1,
        w_ih2, w_hh2, b_ih2, b_hh2,
        w_lin, b_lin, (float*)d_out, T, F);
}

// round 11
// speedup vs baseline: 2.4851x; 1.0772x over previous
#include <cuda_runtime.h>

#define B_TOT 2048
#define H     51
#define HP    52           // padded gate rows (row 51 = zeros)
#define KP    56           // padded k stride per row (floats)
#define KU2   14           // KP in ulonglong2 units
#define PAIR  120          // floats per j-row-pair (2*56 + 8 pad)
#define NJG   26           // j-row-pair groups (covers 52 rows)
#define WSZ   (NJG*PAIR)   // floats per padded gate matrix = 3120
#define E     16           // elements per block
#define TPB   224          // 7 warps: kh(2) x eg(4) x jg(26, tail clones)
#define XCH   40

typedef unsigned long long ull;

struct __align__(16) Smem {
    float l1r[WSZ], l1z[WSZ], l1n[WSZ];      // w_hh1
    float ir2[WSZ], iz2[WSZ], in2[WSZ];      // w_ih2
    float hr2[WSZ], hz2[WSZ], hn2[WSZ];      // w_hh2
    float wih1r[HP], wih1z[HP], wih1n[HP];
    float bR1[HP], bZ1[HP], bIN1[HP], bHN1[HP];
    float bR2[HP], bZ2[HP], bIN2[HP], bHN2[HP];
    float wlin[KP];
    float h1[2][E][KP];                      // state s lives in buf s&1, pads 0
    float h2[2][E][KP];
    float xbuf[E][XCH];
    float PO[4][4][8];                       // out-dot partials [eg][ei][warp], slot 7 = 0
    float blin;
};

__device__ __forceinline__ void fma2(ull& d, ull a, ull b) {
    asm("fma.rn.f32x2 %0, %1, %2, %0;" : "+l"(d) : "l"(a), "l"(b));
}
__device__ __forceinline__ ull pack2(float a, float b) {
    ull r; asm("mov.b64 %0, {%1,%2};" : "=l"(r) : "f"(a), "f"(b)); return r;
}
__device__ __forceinline__ float sum2(ull v) {
    float a, b; asm("mov.b64 {%0,%1}, %2;" : "=f"(a), "=f"(b) : "l"(v));
    return a + b;
}
__device__ __forceinline__ float sigmoid_(float v) {
    return __fdividef(1.0f, 1.0f + __expf(-v));
}
__device__ __forceinline__ float tanh_(float v) {
    return __fdividef(2.0f, 1.0f + __expf(-2.0f * v)) - 1.0f;
}
__device__ __forceinline__ float gru_cell(float gr, float gz, float gin,
                                          float ghn, float ho) {
    float r = sigmoid_(gr);
    float z = sigmoid_(gz);
    float n = tanh_(fmaf(r, ghn, gin));
    return fmaf(z, ho - n, n);
}
__device__ __forceinline__ float xred(ull a0, ull a1, int kh) {
    ull keep = kh ? a1 : a0;
    ull send = kh ? a0 : a1;
    float sf = sum2(send);
    return sum2(keep) + __shfl_xor_sync(0xFFFFFFFFu, sf, 1);
}

__device__ __forceinline__ void fill_mat(float* dst, const float* src, int g, int tid) {
    for (int idx = tid; idx < WSZ; idx += TPB) {
        int jg = idx / PAIR, rem = idx - jg * PAIR;
        int jj = rem / KP;
        int k  = rem - jj * KP;
        float v = 0.f;
        if (jj < 2) {
            int j = jg * 2 + jj;
            if (j < H && k < H) v = src[(g * H + j) * H + k];
        }
        dst[idx] = v;
    }
}

__device__ __forceinline__ float outdot(Smem* s, const float* hrow) {
    const ulonglong2* hv = (const ulonglong2*)hrow;
    const ulonglong2* wl = (const ulonglong2*)s->wlin;
    ull acc = pack2(s->blin, 0.f);
    #pragma unroll
    for (int k = 0; k < KU2; k++) {
        ulonglong2 h = hv[k], w = wl[k];
        fma2(acc, h.x, w.x); fma2(acc, h.y, w.y);
    }
    return sum2(acc);
}

__device__ __forceinline__ float posum(Smem* s, int eg_, int ei_) {
    const float4* p = (const float4*)&s->PO[eg_][ei_][0];
    float4 a = p[0], b = p[1];
    return s->blin + a.x + a.y + a.z + a.w + b.x + b.y + b.z + b.w;
}

__device__ __forceinline__ void layer1(Smem* s, int rd, int wr, const float* xv,
                                       int jg, int j0, int jme, int kh, int kb, int eg)
{
    ull aR[2][4], aZ[2][4], aN[2][4];
    #pragma unroll
    for (int jj = 0; jj < 2; jj++)
        #pragma unroll
        for (int ei = 0; ei < 4; ei++) {
            aR[jj][ei] = (kh == 0) ? pack2(s->bR1[j0 + jj], 0.f) : 0ull;
            aZ[jj][ei] = (kh == 0) ? pack2(s->bZ1[j0 + jj], 0.f) : 0ull;
            aN[jj][ei] = (kh == 0) ? pack2(s->bHN1[j0 + jj], 0.f) : 0ull;
        }
    const ulonglong2* pr = (const ulonglong2*)&s->l1r[jg * PAIR] + kb;
    const ulonglong2* pz = (const ulonglong2*)&s->l1z[jg * PAIR] + kb;
    const ulonglong2* pn = (const ulonglong2*)&s->l1n[jg * PAIR] + kb;
    const ulonglong2* ph = (const ulonglong2*)&s->h1[rd][0][0] + eg * KU2 + kb;
    #pragma unroll
    for (int ki = 0; ki < 7; ki++) {
        ulonglong2 w[6];
        w[0] = pr[ki]; w[1] = pr[ki + KU2];
        w[2] = pz[ki]; w[3] = pz[ki + KU2];
        w[4] = pn[ki]; w[5] = pn[ki + KU2];
        ulonglong2 hv[4];
        #pragma unroll
        for (int ei = 0; ei < 4; ei++) hv[ei] = ph[ki + ei * 4 * KU2];
        #pragma unroll
        for (int jj = 0; jj < 2; jj++)
            #pragma unroll
            for (int ei = 0; ei < 4; ei++) {
                fma2(aR[jj][ei], hv[ei].x, w[0 + jj].x); fma2(aR[jj][ei], hv[ei].y, w[0 + jj].y);
                fma2(aZ[jj][ei], hv[ei].x, w[2 + jj].x); fma2(aZ[jj][ei], hv[ei].y, w[2 + jj].y);
                fma2(aN[jj][ei], hv[ei].x, w[4 + jj].x); fma2(aN[jj][ei], hv[ei].y, w[4 + jj].y);
            }
    }
    float gr[4], gz[4], gn[4];
    #pragma unroll
    for (int ei = 0; ei < 4; ei++) {
        gr[ei] = xred(aR[0][ei], aR[1][ei], kh);
        gz[ei] = xred(aZ[0][ei], aZ[1][ei], kh);
        gn[ei] = xred(aN[0][ei], aN[1][ei], kh);
    }
    const float wr1 = s->wih1r[jme], wz1 = s->wih1z[jme];
    const float wn1 = s->wih1n[jme], bi  = s->bIN1[jme];
    #pragma unroll
    for (int ei = 0; ei < 4; ei++) {
        int el = eg + 4 * ei;
        float ho = s->h1[rd][el][jme];
        float nh = gru_cell(fmaf(xv[ei], wr1, gr[ei]), fmaf(xv[ei], wz1, gz[ei]),
                            fmaf(xv[ei], wn1, bi), gn[ei], ho);
        s->h1[wr][el][jme] = nh;
    }
}

template<bool PO>
__device__ __forceinline__ void layer2(Smem* s, int ub, int vrd, int vwr,
                                       int jg, int j0, int jme, int kh, int kb,
                                       int eg, int lane, int warp, bool clone)
{
    ull aR[2][4], aZ[2][4], aI[2][4], aH[2][4];
    #pragma unroll
    for (int jj = 0; jj < 2; jj++)
        #pragma unroll
        for (int ei = 0; ei < 4; ei++) {
            aR[jj][ei] = (kh == 0) ? pack2(s->bR2[j0 + jj], 0.f) : 0ull;
            aZ[jj][ei] = (kh == 0) ? pack2(s->bZ2[j0 + jj], 0.f) : 0ull;
            aI[jj][ei] = (kh == 0) ? pack2(s->bIN2[j0 + jj], 0.f) : 0ull;
            aH[jj][ei] = (kh == 0) ? pack2(s->bHN2[j0 + jj], 0.f) : 0ull;
        }
    const ulonglong2* pir = (const ulonglong2*)&s->ir2[jg * PAIR] + kb;
    const ulonglong2* piz = (const ulonglong2*)&s->iz2[jg * PAIR] + kb;
    const ulonglong2* pin = (const ulonglong2*)&s->in2[jg * PAIR] + kb;
    const ulonglong2* phr = (const ulonglong2*)&s->hr2[jg * PAIR] + kb;
    const ulonglong2* phz = (const ulonglong2*)&s->hz2[jg * PAIR] + kb;
    const ulonglong2* phn = (const ulonglong2*)&s->hn2[jg * PAIR] + kb;
    const ulonglong2* pu  = (const ulonglong2*)&s->h1[ub][0][0]  + eg * KU2 + kb;
    const ulonglong2* pv  = (const ulonglong2*)&s->h2[vrd][0][0] + eg * KU2 + kb;
    #pragma unroll
    for (int ki = 0; ki < 7; ki++) {
        ulonglong2 wi[6], wh[6];
        wi[0] = pir[ki]; wi[1] = pir[ki + KU2];
        wi[2] = piz[ki]; wi[3] = piz[ki + KU2];
        wi[4] = pin[ki]; wi[5] = pin[ki + KU2];
        wh[0] = phr[ki]; wh[1] = phr[ki + KU2];
        wh[2] = phz[ki]; wh[3] = phz[ki + KU2];
        wh[4] = phn[ki]; wh[5] = phn[ki + KU2];
        ulonglong2 uv[4], vv[4];
        #pragma unroll
        for (int ei = 0; ei < 4; ei++) {
            uv[ei] = pu[ki + ei * 4 * KU2];
            vv[ei] = pv[ki + ei * 4 * KU2];
        }
        #pragma unroll
        for (int jj = 0; jj < 2; jj++)
            #pragma unroll
            for (int ei = 0; ei < 4; ei++) {
                fma2(aR[jj][ei], uv[ei].x, wi[0 + jj].x); fma2(aR[jj][ei], uv[ei].y, wi[0 + jj].y);
                fma2(aR[jj][ei], vv[ei].x, wh[0 + jj].x); fma2(aR[jj][ei], vv[ei].y, wh[0 + jj].y);
                fma2(aZ[jj][ei], uv[ei].x, wi[2 + jj].x); fma2(aZ[jj][ei], uv[ei].y, wi[2 + jj].y);
                fma2(aZ[jj][ei], vv[ei].x, wh[2 + jj].x); fma2(aZ[jj][ei], vv[ei].y, wh[2 + jj].y);
                fma2(aI[jj][ei], uv[ei].x, wi[4 + jj].x); fma2(aI[jj][ei], uv[ei].y, wi[4 + jj].y);
                fma2(aH[jj][ei], vv[ei].x, wh[4 + jj].x); fma2(aH[jj][ei], vv[ei].y, wh[4 + jj].y);
            }
    }
    float gr[4], gz[4], gi[4], gh[4];
    #pragma unroll
    for (int ei = 0; ei < 4; ei++) {
        gr[ei] = xred(aR[0][ei], aR[1][ei], kh);
        gz[ei] = xred(aZ[0][ei], aZ[1][ei], kh);
        gi[ei] = xred(aI[0][ei], aI[1][ei], kh);
        gh[ei] = xred(aH[0][ei], aH[1][ei], kh);
    }
    float nh[4];
    #pragma unroll
    for (int ei = 0; ei < 4; ei++) {
        int el = eg + 4 * ei;
        float ho = s->h2[vrd][el][jme];
        nh[ei] = gru_cell(gr[ei], gz[ei], gi[ei], gh[ei], ho);
        s->h2[vwr][el][jme] = nh[ei];
    }
    if (PO) {
        float wlj = s->wlin[jme];
        float p[4];
        #pragma unroll
        for (int ei = 0; ei < 4; ei++) p[ei] = clone ? 0.f : nh[ei] * wlj;
        #pragma unroll
        for (int ei = 0; ei < 4; ei++) {
            p[ei] += __shfl_xor_sync(0xFFFFFFFFu, p[ei], 1);
            p[ei] += __shfl_xor_sync(0xFFFFFFFFu, p[ei], 8);
            p[ei] += __shfl_xor_sync(0xFFFFFFFFu, p[ei], 16);
        }
        if ((lane & 25) == 0) {      // kh==0 && jg-within-warp==0
            s->PO[eg][0][warp] = p[0];
            s->PO[eg][1][warp] = p[1];
            s->PO[eg][2][warp] = p[2];
            s->PO[eg][3][warp] = p[3];
        }
    }
}

__global__ void __launch_bounds__(TPB, 1) gru_stack_kernel(
    const float* __restrict__ x,
    const float* __restrict__ w_ih1, const float* __restrict__ w_hh1,
    const float* __restrict__ b_ih1, const float* __restrict__ b_hh1,
    const float* __restrict__ w_ih2, const float* __restrict__ w_hh2,
    const float* __restrict__ b_ih2, const float* __restrict__ b_hh2,
    const float* __restrict__ w_lin, const float* __restrict__ b_lin,
    float* __restrict__ out, int T, int F)
{
    extern __shared__ float smem_f[];
    Smem* s = reinterpret_cast<Smem*>(smem_f);

    const int tid  = threadIdx.x;
    const int kh   = tid & 1;
    const int eg   = (tid >> 1) & 3;
    const int jgr  = tid >> 3;
    const bool clone = (jgr > NJG - 1);
    const int jg   = clone ? NJG - 1 : jgr;
    const int j0   = 2 * jg;
    const int jme  = j0 + kh;
    const int kb   = kh * (KU2 / 2);
    const int lane = tid & 31;
    const int warp = tid >> 5;
    const int base = blockIdx.x * E;
    const int TF   = T + F;

    // ---------------- one-time init ----------------
    fill_mat(s->l1r, w_hh1, 0, tid); fill_mat(s->l1z, w_hh1, 1, tid); fill_mat(s->l1n, w_hh1, 2, tid);
    fill_mat(s->ir2, w_ih2, 0, tid); fill_mat(s->iz2, w_ih2, 1, tid); fill_mat(s->in2, w_ih2, 2, tid);
    fill_mat(s->hr2, w_hh2, 0, tid); fill_mat(s->hz2, w_hh2, 1, tid); fill_mat(s->hn2, w_hh2, 2, tid);
    for (int i = tid; i < HP; i += TPB) {
        bool v = (i < H);
        s->wih1r[i] = v ? w_ih1[i] : 0.f;
        s->wih1z[i] = v ? w_ih1[H + i] : 0.f;
        s->wih1n[i] = v ? w_ih1[2 * H + i] : 0.f;
        s->bR1[i]  = v ? (b_ih1[i] + b_hh1[i]) : 0.f;
        s->bZ1[i]  = v ? (b_ih1[H + i] + b_hh1[H + i]) : 0.f;
        s->bIN1[i] = v ? b_ih1[2 * H + i] : 0.f;
        s->bHN1[i] = v ? b_hh1[2 * H + i] : 0.f;
        s->bR2[i]  = v ? (b_ih2[i] + b_hh2[i]) : 0.f;
        s->bZ2[i]  = v ? (b_ih2[H + i] + b_hh2[H + i]) : 0.f;
        s->bIN2[i] = v ? b_ih2[2 * H + i] : 0.f;
        s->bHN2[i] = v ? b_hh2[2 * H + i] : 0.f;
    }
    for (int i = tid; i < KP; i += TPB) s->wlin[i] = (i < H) ? w_lin[i] : 0.f;
    if (tid == 0) s->blin = b_lin[0];
    {
        float* h1f = &s->h1[0][0][0];
        float* h2f = &s->h2[0][0][0];
        for (int i = tid; i < 2 * E * KP; i += TPB) { h1f[i] = 0.f; h2f[i] = 0.f; }
        float* pof = &s->PO[0][0][0];
        for (int i = tid; i < 128; i += TPB) pof[i] = 0.f;
    }
    __syncthreads();

    // ================= phase 1 (teacher forced): 1 interval per step =================
    // interval i: out(i-2) [tid<E] ; L1(i) ; L2(i-1)   — all independent
    for (int i = 0; i < T; ++i) {
        if ((i % XCH) == 0) {
            for (int k = tid; k < E * XCH; k += TPB) {
                int e = k / XCH, c = k - e * XCH;
                int tg = i + c;
                s->xbuf[e][c] = (tg < T) ? x[(size_t)(base + e) * T + tg] : 0.f;
            }
            __syncthreads();
        }
        const int xidx = i % XCH;
        if (i >= 2 && tid < E)
            out[(size_t)(base + tid) * TF + (i - 2)] = outdot(s, &s->h2[i & 1][tid][0]);
        float xv[4];
        #pragma unroll
        for (int ei = 0; ei < 4; ei++) xv[ei] = s->xbuf[eg + 4 * ei][xidx];
        layer1(s, (i + 1) & 1, i & 1, xv, jg, j0, jme, kh, kb, eg);
        if (i >= 1)
            layer2<false>(s, (i + 1) & 1, i & 1, (i + 1) & 1,
                          jg, j0, jme, kh, kb, eg, lane, warp, clone);
        __syncthreads();
    }
    // tail interval: L2(T-1) (+PO for phase-2 start), out(T-2)
    if (tid < E)
        out[(size_t)(base + tid) * TF + (T - 2)] = outdot(s, &s->h2[T & 1][tid][0]);
    layer2<true>(s, (T + 1) & 1, T & 1, (T + 1) & 1,
                 jg, j0, jme, kh, kb, eg, lane, warp, clone);
    __syncthreads();

    // ================= phase 2 (autoregressive): 2 intervals per step =================
    for (int t = T; t < TF; ++t) {
        // interval A: L1(t) with xv = out(t-1) summed inline from PO; emit out(t-1)
        float xv[4];
        #pragma unroll
        for (int ei = 0; ei < 4; ei++) xv[ei] = posum(s, eg, ei);
        layer1(s, (t + 1) & 1, t & 1, xv, jg, j0, jme, kh, kb, eg);
        if (tid < E)
            out[(size_t)(base + tid) * TF + (t - 1)] = posum(s, tid & 3, tid >> 2);
        __syncthreads();
        // interval B: L2(t) + PO(h2(t))
        layer2<true>(s, t & 1, (t + 1) & 1, t & 1,
                     jg, j0, jme, kh, kb, eg, lane, warp, clone);
        __syncthreads();
    }

    // final output (step TF-1)
    if (tid < E)
        out[(size_t)(base + tid) * TF + (TF - 1)] = outdot(s, &s->h2[(TF - 1) & 1][tid][0]);
}

extern "C" void kernel_launch(void* const* d_in, const int* in_sizes, int n_in,
                              void* d_out, int out_size)
{
    const float* x     = (const float*)d_in[0];
    const float* w_ih1 = (const float*)d_in[1];
    const float* w_hh1 = (const float*)d_in[2];
    const float* b_ih1 = (const float*)d_in[3];
    const float* b_hh1 = (const float*)d_in[4];
    const float* w_ih2 = (const float*)d_in[5];
    const float* w_hh2 = (const float*)d_in[6];
    const float* b_ih2 = (const float*)d_in[7];
    const float* b_hh2 = (const float*)d_in[8];
    const float* w_lin = (const float*)d_in[9];
    const float* b_lin = (const float*)d_in[10];

    const int B  = B_TOT;
    const int T  = in_sizes[0] / B;
    const int TF = out_size / B;
    const int F  = TF - T;

    size_t shmem = sizeof(Smem);
    cudaFuncSetAttribute(gru_stack_kernel,
                         cudaFuncAttributeMaxDynamicSharedMemorySize, (int)shmem);

    gru_stack_kernel<<<B / E, TPB, shmem>>>(
        x, w_ih1, w_hh1, b_ih1, b_hh1,
        w_ih2, w_hh2, b_ih2, b_hh2,
        w_lin, b_lin, (float*)d_out, T, F);
}